// round 2
// baseline (speedup 1.0000x reference)
#include <cuda_runtime.h>
#include <cuda_bf16.h>

#define B_ 16
#define N_ 512
#define L_ 2048
#define DIM_ 768
#define M_ 8
#define CE_ 64
#define VOCAB_ 1024
#define H_ 128
#define G4H_ (4*H_)   // 512

// ---------------- scratch (device globals: no allocations allowed) ----------
__device__ float g_rep [B_*N_*M_*CE_];    // [B,N,512]  word char projections
__device__ float g_xcat[B_*L_*2*CE_];     // [B,L,128]  lstm input (char | padded)
__device__ float g_xpre[B_*L_*G4H_];      // [B,L,512]  x@W_ih^T + b_ih + b_hh
__device__ float g_hs  [B_*L_*H_];        // [B,L,128]  lstm hidden states
__device__ float g_WihT[2*CE_*G4H_];      // [128,512]  W_ih transposed
__device__ float g_bias2[G4H_];           // b_ih + b_hh
__device__ int   g_woff[B_*N_];           // exclusive prefix sum of word lens

// ---------------- f32x2 helpers ---------------------------------------------
static __device__ __forceinline__ unsigned long long pack2(float lo, float hi) {
    unsigned long long r;
    asm("mov.b64 %0, {%1, %2};" : "=l"(r) : "f"(lo), "f"(hi));
    return r;
}
static __device__ __forceinline__ unsigned long long pack2dup(float a) {
    unsigned long long r;
    asm("mov.b64 %0, {%1, %1};" : "=l"(r) : "f"(a));
    return r;
}
static __device__ __forceinline__ float2 unpack2(unsigned long long v) {
    float2 r;
    asm("mov.b64 {%0, %1}, %2;" : "=f"(r.x), "=f"(r.y) : "l"(v));
    return r;
}
static __device__ __forceinline__ unsigned long long ffma2(
    unsigned long long a, unsigned long long b, unsigned long long c) {
    unsigned long long d;
    asm("fma.rn.f32x2 %0, %1, %2, %3;" : "=l"(d) : "l"(a), "l"(b), "l"(c));
    return d;
}

// ---------------- prep: transpose W_ih, combine biases -----------------------
__global__ void prep_kernel(const float* __restrict__ W_ih,
                            const float* __restrict__ b_ih,
                            const float* __restrict__ b_hh) {
    int i = blockIdx.x * blockDim.x + threadIdx.x;
    if (i < G4H_ * 2 * CE_) {
        int g = i / (2 * CE_), k = i % (2 * CE_);
        g_WihT[k * G4H_ + g] = W_ih[g * (2 * CE_) + k];
    }
    if (i < G4H_) g_bias2[i] = b_ih[i] + b_hh[i];
}

// ---------------- per-batch exclusive prefix sum of word lens ---------------
__global__ void scan_lens_kernel(const int* __restrict__ lens) {
    __shared__ int s[N_];
    int b = blockIdx.x, tid = threadIdx.x;
    int v0 = lens[b * N_ + tid];
    s[tid] = v0;
    __syncthreads();
    #pragma unroll
    for (int off = 1; off < N_; off <<= 1) {
        int v = (tid >= off) ? s[tid - off] : 0;
        __syncthreads();
        s[tid] += v;
        __syncthreads();
    }
    g_woff[b * N_ + tid] = s[tid] - v0;   // exclusive
}

// ---------------- build x_cat: char embedding + zero padded half ------------
__global__ void build_char_kernel(const int* __restrict__ ids,
                                  const float* __restrict__ emb) {
    long i = (long)blockIdx.x * blockDim.x + threadIdx.x;   // one float4 each
    if (i >= (long)B_ * L_ * 32) return;
    int q = (int)(i & 31);
    long bt = i >> 5;
    float4* dst = (float4*)(g_xcat + bt * 128);
    if (q < 16) {
        int id = ids[bt];
        dst[q] = ((const float4*)(emb + (long)id * CE_))[q];
    } else {
        dst[q] = make_float4(0.f, 0.f, 0.f, 0.f);
    }
}

// ---------------- ragged scatter of word char projections -------------------
__global__ void scatter_pad_kernel(const int* __restrict__ lens) {
    int w = (blockIdx.x * blockDim.x + threadIdx.x) >> 5;   // one warp per word
    int lane = threadIdx.x & 31;
    if (w >= B_ * N_) return;
    int b = w / N_;
    int len = lens[w];
    int off = g_woff[w];
    for (int m = 0; m < len; m++) {
        int pos = off + m;
        if (pos >= L_) break;
        const float2* src = (const float2*)(g_rep + ((long)w * M_ + m) * CE_);
        float2* dst = (float2*)(g_xcat + ((long)b * L_ + pos) * 128 + CE_);
        dst[lane] = src[lane];
    }
}

// ---------------- fp32 GEMM (f32x2 FFMA), C = A@B + bias --------------------
// A [M,K] row-major, B [K,N] row-major, all tile dims divide exactly.
#define BM 128
#define BN 128
#define BK 16

__global__ __launch_bounds__(256, 2)
void sgemm_bias_kernel(int M, int N, int K,
                       const float* __restrict__ A,
                       const float* __restrict__ B,
                       const float* __restrict__ bias,
                       float* __restrict__ C) {
    __shared__ float As[BK][BM];
    __shared__ float Bs[BK][BN];
    int tid = threadIdx.x;
    int bx = blockIdx.x, by = blockIdx.y;
    int tx = tid & 15, ty = tid >> 4;

    const float* Ablk = A + (long)by * BM * K;
    const float* Bblk = B + bx * BN;

    unsigned long long acc[8][4];
    #pragma unroll
    for (int i = 0; i < 8; i++)
        #pragma unroll
        for (int j = 0; j < 4; j++) acc[i][j] = 0ull;   // two packed +0.0f

    int arow = tid >> 2;          // 0..63 (and +64)
    int acol4 = tid & 3;          // 0..3
    int brow = tid >> 5;          // 0..7 (and +8)
    int bcol4 = tid & 31;         // 0..31

    for (int k0 = 0; k0 < K; k0 += BK) {
        float4 a0 = *(const float4*)(Ablk + (long)arow * K + k0 + 4 * acol4);
        float4 a1 = *(const float4*)(Ablk + (long)(arow + 64) * K + k0 + 4 * acol4);
        float4 b0 = *(const float4*)(Bblk + (long)(k0 + brow) * N + 4 * bcol4);
        float4 b1 = *(const float4*)(Bblk + (long)(k0 + brow + 8) * N + 4 * bcol4);
        __syncthreads();
        As[4 * acol4 + 0][arow] = a0.x;
        As[4 * acol4 + 1][arow] = a0.y;
        As[4 * acol4 + 2][arow] = a0.z;
        As[4 * acol4 + 3][arow] = a0.w;
        As[4 * acol4 + 0][arow + 64] = a1.x;
        As[4 * acol4 + 1][arow + 64] = a1.y;
        As[4 * acol4 + 2][arow + 64] = a1.z;
        As[4 * acol4 + 3][arow + 64] = a1.w;
        *(float4*)&Bs[brow][4 * bcol4] = b0;
        *(float4*)&Bs[brow + 8][4 * bcol4] = b1;
        __syncthreads();
        #pragma unroll
        for (int k = 0; k < BK; k++) {
            float4 af0 = *(const float4*)&As[k][4 * ty];
            float4 af1 = *(const float4*)&As[k][64 + 4 * ty];
            ulonglong2 bf0 = *(const ulonglong2*)&Bs[k][4 * tx];
            ulonglong2 bf1 = *(const ulonglong2*)&Bs[k][64 + 4 * tx];
            float ar[8] = {af0.x, af0.y, af0.z, af0.w, af1.x, af1.y, af1.z, af1.w};
            unsigned long long b2[4] = {bf0.x, bf0.y, bf1.x, bf1.y};
            #pragma unroll
            for (int i = 0; i < 8; i++) {
                unsigned long long ad = pack2dup(ar[i]);
                #pragma unroll
                for (int j = 0; j < 4; j++)
                    acc[i][j] = ffma2(ad, b2[j], acc[i][j]);
            }
        }
    }

    #pragma unroll
    for (int i = 0; i < 8; i++) {
        int r = by * BM + (i < 4 ? 4 * ty + i : 64 + 4 * ty + (i - 4));
        #pragma unroll
        for (int j2 = 0; j2 < 4; j2++) {
            int cb = bx * BN + (j2 < 2 ? 4 * tx + 2 * j2 : 64 + 4 * tx + 2 * (j2 - 2));
            float2 v = unpack2(acc[i][j2]);
            float2 o;
            o.x = v.x + bias[cb];
            o.y = v.y + bias[cb + 1];
            *(float2*)&C[(long)r * N + cb] = o;
        }
    }
}

// ---------------- LSTM recurrence: one CTA per batch ------------------------
// Thread j computes gate row j (512 gates). W_hh row j: first 64 weights in
// registers (32 packed f32x2), last 64 in smem k-major (conflict-free LDS.128).
#define LSTM_SMEM (16 * G4H_ * (int)sizeof(ulonglong2) + (H_ + G4H_) * (int)sizeof(float))

__global__ __launch_bounds__(512, 1)
void lstm_rec_kernel(const float* __restrict__ Whh) {
    extern __shared__ char smem_raw[];
    ulonglong2 (*wsm)[G4H_] = (ulonglong2(*)[G4H_])smem_raw;             // [16][512]
    float* h_sm = (float*)(smem_raw + 16 * G4H_ * sizeof(ulonglong2));   // [128]
    float* g_sm = h_sm + H_;                                             // [512]

    int b = blockIdx.x;
    int j = threadIdx.x;

    // load weights: regs = W_hh[j][0:64], smem = W_hh[j][64:128]
    unsigned long long wr[32];
    const unsigned long long* wrow = (const unsigned long long*)(Whh + (long)j * H_);
    #pragma unroll
    for (int k2 = 0; k2 < 32; k2++) wr[k2] = wrow[k2];
    const ulonglong2* wrow2 = (const ulonglong2*)(Whh + (long)j * H_ + 64);
    #pragma unroll
    for (int k4 = 0; k4 < 16; k4++) wsm[k4][j] = wrow2[k4];

    float c = 0.f;
    if (j < H_) h_sm[j] = 0.f;
    __syncthreads();

    const float* xp = g_xpre + (long)b * L_ * G4H_ + j;
    float xr = xp[0];

    for (int t = 0; t < L_; t++) {
        int tn = (t + 1 < L_) ? t + 1 : t;
        float xr_next = xp[(long)tn * G4H_];

        unsigned long long acc = pack2(xr, 0.f);
        const ulonglong2* h2 = (const ulonglong2*)h_sm;
        #pragma unroll
        for (int k4 = 0; k4 < 16; k4++) {
            ulonglong2 hv = h2[k4];
            acc = ffma2(hv.x, wr[2 * k4], acc);
            acc = ffma2(hv.y, wr[2 * k4 + 1], acc);
        }
        #pragma unroll
        for (int k4 = 0; k4 < 16; k4++) {
            ulonglong2 hv = h2[16 + k4];
            ulonglong2 wv = wsm[k4][j];
            acc = ffma2(hv.x, wv.x, acc);
            acc = ffma2(hv.y, wv.y, acc);
        }
        float2 av = unpack2(acc);
        g_sm[j] = av.x + av.y;
        __syncthreads();

        if (j < H_) {
            float gi = g_sm[j];
            float gf = g_sm[H_ + j];
            float gg = g_sm[2 * H_ + j];
            float go = g_sm[3 * H_ + j];
            float si = 1.f / (1.f + __expf(-gi));
            float sf = 1.f / (1.f + __expf(-gf));
            float tg = tanhf(gg);
            float so = 1.f / (1.f + __expf(-go));
            c = sf * c + si * tg;
            float h = so * tanhf(c);
            h_sm[j] = h;
            g_hs[((long)b * L_ + t) * H_ + j] = h;
        }
        __syncthreads();
        xr = xr_next;
    }
}

// ---------------- launch ----------------------------------------------------
extern "C" void kernel_launch(void* const* d_in, const int* in_sizes, int n_in,
                              void* d_out, int out_size) {
    const float* dec_hidden = (const float*)d_in[0];
    const int*   ids        = (const int*)d_in[1];
    const int*   lens       = (const int*)d_in[2];
    const float* char_emb   = (const float*)d_in[3];
    const float* W_proj     = (const float*)d_in[4];
    const float* b_proj     = (const float*)d_in[5];
    const float* W_ih       = (const float*)d_in[6];
    const float* W_hh       = (const float*)d_in[7];
    const float* b_ih       = (const float*)d_in[8];
    const float* b_hh       = (const float*)d_in[9];
    const float* W_pred     = (const float*)d_in[10];
    const float* b_pred     = (const float*)d_in[11];
    float* out = (float*)d_out;

    // device-global scratch addresses (host side)
    float *p_rep, *p_xcat, *p_xpre, *p_hs, *p_WihT, *p_bias2;
    cudaGetSymbolAddress((void**)&p_rep,   g_rep);
    cudaGetSymbolAddress((void**)&p_xcat,  g_xcat);
    cudaGetSymbolAddress((void**)&p_xpre,  g_xpre);
    cudaGetSymbolAddress((void**)&p_hs,    g_hs);
    cudaGetSymbolAddress((void**)&p_WihT,  g_WihT);
    cudaGetSymbolAddress((void**)&p_bias2, g_bias2);

    // 0) prep: transpose W_ih, combine biases
    prep_kernel<<<(G4H_ * 2 * CE_ + 255) / 256, 256>>>(W_ih, b_ih, b_hh);

    // 1) word-length prefix sums
    scan_lens_kernel<<<B_, N_>>>(lens);

    // 2) proj GEMM: rep = dec_hidden @ W_proj + b_proj   [8192,768]@[768,512]
    sgemm_bias_kernel<<<dim3(G4H_ / BN, (B_ * N_) / BM), 256>>>(
        B_ * N_, M_ * CE_, DIM_, dec_hidden, W_proj, b_proj, p_rep);

    // 3) build x_cat: char half + zero padded half, then ragged scatter
    build_char_kernel<<<(B_ * L_ * 32) / 256, 256>>>(ids, char_emb);
    scatter_pad_kernel<<<(B_ * N_ * 32) / 256, 256>>>(lens);

    // 4) LSTM input pre-GEMM: xpre = x_cat @ W_ih^T + (b_ih+b_hh)
    sgemm_bias_kernel<<<dim3(G4H_ / BN, (B_ * L_) / BM), 256>>>(
        B_ * L_, G4H_, 2 * CE_, p_xcat, p_WihT, p_bias2, p_xpre);

    // 5) recurrence (one CTA per batch)
    cudaFuncSetAttribute(lstm_rec_kernel,
                         cudaFuncAttributeMaxDynamicSharedMemorySize, LSTM_SMEM);
    lstm_rec_kernel<<<B_, 512, LSTM_SMEM>>>(W_hh);

    // 6) prediction GEMM: out = hs @ W_pred + b_pred   [32768,128]@[128,1024]
    sgemm_bias_kernel<<<dim3(VOCAB_ / BN, (B_ * L_) / BM), 256>>>(
        B_ * L_, VOCAB_, H_, p_hs, W_pred, b_pred, out);
}

// round 6
// speedup vs baseline: 1.4137x; 1.4137x over previous
#include <cuda_runtime.h>
#include <cuda_bf16.h>

#define B_ 16
#define N_ 512
#define L_ 2048
#define DIM_ 768
#define M_ 8
#define CE_ 64
#define VOCAB_ 1024
#define H_ 128
#define G4H_ (4*H_)   // 512

// ---------------- scratch (device globals: no allocations allowed) ----------
__device__ float g_rep [B_*N_*M_*CE_];    // [B,N,512]  word char projections
__device__ float g_xcat[B_*L_*2*CE_];     // [B,L,128]  lstm input (char | padded)
__device__ float g_xpre[B_*L_*G4H_];      // [B,L,512]  x@W_ih^T + b_ih + b_hh
__device__ float g_hs  [B_*L_*H_];        // [B,L,128]  lstm hidden states
__device__ float g_WihT[2*CE_*G4H_];      // [128,512]  W_ih transposed
__device__ float g_bias2[G4H_];           // b_ih + b_hh
__device__ int   g_woff[B_*N_];           // exclusive prefix sum of word lens

// ---------------- f32x2 helpers ---------------------------------------------
static __device__ __forceinline__ unsigned long long pack2(float lo, float hi) {
    unsigned long long r;
    asm("mov.b64 %0, {%1, %2};" : "=l"(r) : "f"(lo), "f"(hi));
    return r;
}
static __device__ __forceinline__ unsigned long long pack2dup(float a) {
    unsigned long long r;
    asm("mov.b64 %0, {%1, %1};" : "=l"(r) : "f"(a));
    return r;
}
static __device__ __forceinline__ float2 unpack2(unsigned long long v) {
    float2 r;
    asm("mov.b64 {%0, %1}, %2;" : "=f"(r.x), "=f"(r.y) : "l"(v));
    return r;
}
static __device__ __forceinline__ unsigned long long ffma2(
    unsigned long long a, unsigned long long b, unsigned long long c) {
    unsigned long long d;
    asm("fma.rn.f32x2 %0, %1, %2, %3;" : "=l"(d) : "l"(a), "l"(b), "l"(c));
    return d;
}
static __device__ __forceinline__ float fast_tanh(float x) {
    float r;
    asm("tanh.approx.f32 %0, %1;" : "=f"(r) : "f"(x));
    return r;
}
static __device__ __forceinline__ float fast_sigmoid(float x) {
    // sigmoid(x) = 0.5 * tanh(x/2) + 0.5
    float r;
    asm("tanh.approx.f32 %0, %1;" : "=f"(r) : "f"(0.5f * x));
    return fmaf(0.5f, r, 0.5f);
}

// ---------------- prep: transpose W_ih, combine biases -----------------------
__global__ void prep_kernel(const float* __restrict__ W_ih,
                            const float* __restrict__ b_ih,
                            const float* __restrict__ b_hh) {
    int i = blockIdx.x * blockDim.x + threadIdx.x;
    if (i < G4H_ * 2 * CE_) {
        int g = i / (2 * CE_), k = i % (2 * CE_);
        g_WihT[k * G4H_ + g] = W_ih[g * (2 * CE_) + k];
    }
    if (i < G4H_) g_bias2[i] = b_ih[i] + b_hh[i];
}

// ---------------- per-batch exclusive prefix sum of word lens ---------------
__global__ void scan_lens_kernel(const int* __restrict__ lens) {
    __shared__ int s[N_];
    int b = blockIdx.x, tid = threadIdx.x;
    int v0 = lens[b * N_ + tid];
    s[tid] = v0;
    __syncthreads();
    #pragma unroll
    for (int off = 1; off < N_; off <<= 1) {
        int v = (tid >= off) ? s[tid - off] : 0;
        __syncthreads();
        s[tid] += v;
        __syncthreads();
    }
    g_woff[b * N_ + tid] = s[tid] - v0;   // exclusive
}

// ---------------- build x_cat: char embedding + zero padded half ------------
__global__ void build_char_kernel(const int* __restrict__ ids,
                                  const float* __restrict__ emb) {
    long i = (long)blockIdx.x * blockDim.x + threadIdx.x;   // one float4 each
    if (i >= (long)B_ * L_ * 32) return;
    int q = (int)(i & 31);
    long bt = i >> 5;
    float4* dst = (float4*)(g_xcat + bt * 128);
    if (q < 16) {
        int id = ids[bt];
        dst[q] = ((const float4*)(emb + (long)id * CE_))[q];
    } else {
        dst[q] = make_float4(0.f, 0.f, 0.f, 0.f);
    }
}

// ---------------- ragged scatter of word char projections -------------------
__global__ void scatter_pad_kernel(const int* __restrict__ lens) {
    int w = (blockIdx.x * blockDim.x + threadIdx.x) >> 5;   // one warp per word
    int lane = threadIdx.x & 31;
    if (w >= B_ * N_) return;
    int b = w / N_;
    int len = lens[w];
    int off = g_woff[w];
    for (int m = 0; m < len; m++) {
        int pos = off + m;
        if (pos >= L_) break;
        const float2* src = (const float2*)(g_rep + ((long)w * M_ + m) * CE_);
        float2* dst = (float2*)(g_xcat + ((long)b * L_ + pos) * 128 + CE_);
        dst[lane] = src[lane];
    }
}

// ---------------- fp32 GEMM (f32x2 FFMA), C = A@B + bias --------------------
// A [M,K] row-major, B [K,N] row-major, all tile dims divide exactly.
#define BM 128
#define BN 128
#define BK 16

__global__ __launch_bounds__(256, 2)
void sgemm_bias_kernel(int M, int N, int K,
                       const float* __restrict__ A,
                       const float* __restrict__ B,
                       const float* __restrict__ bias,
                       float* __restrict__ C) {
    __shared__ float As[BK][BM];
    __shared__ float Bs[BK][BN];
    int tid = threadIdx.x;
    int bx = blockIdx.x, by = blockIdx.y;
    int tx = tid & 15, ty = tid >> 4;

    const float* Ablk = A + (long)by * BM * K;
    const float* Bblk = B + bx * BN;

    unsigned long long acc[8][4];
    #pragma unroll
    for (int i = 0; i < 8; i++)
        #pragma unroll
        for (int j = 0; j < 4; j++) acc[i][j] = 0ull;   // two packed +0.0f

    int arow = tid >> 2;          // 0..63 (and +64)
    int acol4 = tid & 3;          // 0..3
    int brow = tid >> 5;          // 0..7 (and +8)
    int bcol4 = tid & 31;         // 0..31

    for (int k0 = 0; k0 < K; k0 += BK) {
        float4 a0 = *(const float4*)(Ablk + (long)arow * K + k0 + 4 * acol4);
        float4 a1 = *(const float4*)(Ablk + (long)(arow + 64) * K + k0 + 4 * acol4);
        float4 b0 = *(const float4*)(Bblk + (long)(k0 + brow) * N + 4 * bcol4);
        float4 b1 = *(const float4*)(Bblk + (long)(k0 + brow + 8) * N + 4 * bcol4);
        __syncthreads();
        As[4 * acol4 + 0][arow] = a0.x;
        As[4 * acol4 + 1][arow] = a0.y;
        As[4 * acol4 + 2][arow] = a0.z;
        As[4 * acol4 + 3][arow] = a0.w;
        As[4 * acol4 + 0][arow + 64] = a1.x;
        As[4 * acol4 + 1][arow + 64] = a1.y;
        As[4 * acol4 + 2][arow + 64] = a1.z;
        As[4 * acol4 + 3][arow + 64] = a1.w;
        *(float4*)&Bs[brow][4 * bcol4] = b0;
        *(float4*)&Bs[brow + 8][4 * bcol4] = b1;
        __syncthreads();
        #pragma unroll
        for (int k = 0; k < BK; k++) {
            float4 af0 = *(const float4*)&As[k][4 * ty];
            float4 af1 = *(const float4*)&As[k][64 + 4 * ty];
            ulonglong2 bf0 = *(const ulonglong2*)&Bs[k][4 * tx];
            ulonglong2 bf1 = *(const ulonglong2*)&Bs[k][64 + 4 * tx];
            float ar[8] = {af0.x, af0.y, af0.z, af0.w, af1.x, af1.y, af1.z, af1.w};
            unsigned long long b2[4] = {bf0.x, bf0.y, bf1.x, bf1.y};
            #pragma unroll
            for (int i = 0; i < 8; i++) {
                unsigned long long ad = pack2dup(ar[i]);
                #pragma unroll
                for (int j = 0; j < 4; j++)
                    acc[i][j] = ffma2(ad, b2[j], acc[i][j]);
            }
        }
    }

    #pragma unroll
    for (int i = 0; i < 8; i++) {
        int r = by * BM + (i < 4 ? 4 * ty + i : 64 + 4 * ty + (i - 4));
        #pragma unroll
        for (int j2 = 0; j2 < 4; j2++) {
            int cb = bx * BN + (j2 < 2 ? 4 * tx + 2 * j2 : 64 + 4 * tx + 2 * (j2 - 2));
            float2 v = unpack2(acc[i][j2]);
            float2 o;
            o.x = v.x + bias[cb];
            o.y = v.y + bias[cb + 1];
            *(float2*)&C[(long)r * N + cb] = o;
        }
    }
}

// ---------------- LSTM recurrence: one CTA per batch ------------------------
// Thread j computes gate row j (512 gates). W_hh row j: first 96 weights in
// registers (48 packed f32x2), last 32 in smem k-major (conflict-free LDS.128).
// smem weight traffic: 64KB/step (was 128KB) -> FMA-issue bound, not smem-BW bound.
#define WSM_QUADS 8   // 8 x ulonglong2 = 32 floats per row in smem
#define LSTM_SMEM (WSM_QUADS * G4H_ * (int)sizeof(ulonglong2) + (H_ + G4H_) * (int)sizeof(float))

__global__ __launch_bounds__(512, 1)
void lstm_rec_kernel(const float* __restrict__ Whh) {
    extern __shared__ char smem_raw[];
    ulonglong2 (*wsm)[G4H_] = (ulonglong2(*)[G4H_])smem_raw;                   // [8][512]
    float* h_sm = (float*)(smem_raw + WSM_QUADS * G4H_ * sizeof(ulonglong2));  // [128]
    float* g_sm = h_sm + H_;                                                   // [512]

    int b = blockIdx.x;
    int j = threadIdx.x;

    // load weights: regs = W_hh[j][0:96], smem = W_hh[j][96:128]
    unsigned long long wr[48];
    const unsigned long long* wrow = (const unsigned long long*)(Whh + (long)j * H_);
    #pragma unroll
    for (int k2 = 0; k2 < 48; k2++) wr[k2] = wrow[k2];
    const ulonglong2* wrow2 = (const ulonglong2*)(Whh + (long)j * H_ + 96);
    #pragma unroll
    for (int k4 = 0; k4 < WSM_QUADS; k4++) wsm[k4][j] = wrow2[k4];

    float c = 0.f;
    if (j < H_) h_sm[j] = 0.f;
    __syncthreads();

    const float* xp = g_xpre + (long)b * L_ * G4H_ + j;
    float xr = xp[0];

    for (int t = 0; t < L_; t++) {
        int tn = (t + 1 < L_) ? t + 1 : t;
        float xr_next = xp[(long)tn * G4H_];

        // two independent accumulator chains (break FFMA RAW latency chain)
        unsigned long long acc0 = pack2(xr, 0.f);
        unsigned long long acc1 = 0ull;
        const ulonglong2* h2 = (const ulonglong2*)h_sm;   // 32 x (2 floats)
        #pragma unroll
        for (int k4 = 0; k4 < 24; k4++) {                 // k = 0..95 from regs
            ulonglong2 hv = h2[k4];
            acc0 = ffma2(hv.x, wr[2 * k4], acc0);
            acc1 = ffma2(hv.y, wr[2 * k4 + 1], acc1);
        }
        #pragma unroll
        for (int k4 = 0; k4 < WSM_QUADS; k4++) {          // k = 96..127 from smem
            ulonglong2 hv = h2[24 + k4];
            ulonglong2 wv = wsm[k4][j];
            acc0 = ffma2(hv.x, wv.x, acc0);
            acc1 = ffma2(hv.y, wv.y, acc1);
        }
        float2 a0 = unpack2(acc0);
        float2 a1 = unpack2(acc1);
        g_sm[j] = (a0.x + a1.x) + (a0.y + a1.y);
        __syncthreads();

        if (j < H_) {
            float gi = g_sm[j];
            float gf = g_sm[H_ + j];
            float gg = g_sm[2 * H_ + j];
            float go = g_sm[3 * H_ + j];
            float si = fast_sigmoid(gi);
            float sf = fast_sigmoid(gf);
            float tg = fast_tanh(gg);
            float so = fast_sigmoid(go);
            c = sf * c + si * tg;
            float h = so * fast_tanh(c);
            h_sm[j] = h;
            g_hs[((long)b * L_ + t) * H_ + j] = h;
        }
        __syncthreads();
        xr = xr_next;
    }
}

// ---------------- launch ----------------------------------------------------
extern "C" void kernel_launch(void* const* d_in, const int* in_sizes, int n_in,
                              void* d_out, int out_size) {
    const float* dec_hidden = (const float*)d_in[0];
    const int*   ids        = (const int*)d_in[1];
    const int*   lens       = (const int*)d_in[2];
    const float* char_emb   = (const float*)d_in[3];
    const float* W_proj     = (const float*)d_in[4];
    const float* b_proj     = (const float*)d_in[5];
    const float* W_ih       = (const float*)d_in[6];
    const float* W_hh       = (const float*)d_in[7];
    const float* b_ih       = (const float*)d_in[8];
    const float* b_hh       = (const float*)d_in[9];
    const float* W_pred     = (const float*)d_in[10];
    const float* b_pred     = (const float*)d_in[11];
    float* out = (float*)d_out;

    // device-global scratch addresses (host side)
    float *p_rep, *p_xcat, *p_xpre, *p_hs, *p_WihT, *p_bias2;
    cudaGetSymbolAddress((void**)&p_rep,   g_rep);
    cudaGetSymbolAddress((void**)&p_xcat,  g_xcat);
    cudaGetSymbolAddress((void**)&p_xpre,  g_xpre);
    cudaGetSymbolAddress((void**)&p_hs,    g_hs);
    cudaGetSymbolAddress((void**)&p_WihT,  g_WihT);
    cudaGetSymbolAddress((void**)&p_bias2, g_bias2);

    // 0) prep: transpose W_ih, combine biases
    prep_kernel<<<(G4H_ * 2 * CE_ + 255) / 256, 256>>>(W_ih, b_ih, b_hh);

    // 1) word-length prefix sums
    scan_lens_kernel<<<B_, N_>>>(lens);

    // 2) proj GEMM: rep = dec_hidden @ W_proj + b_proj   [8192,768]@[768,512]
    sgemm_bias_kernel<<<dim3(G4H_ / BN, (B_ * N_) / BM), 256>>>(
        B_ * N_, M_ * CE_, DIM_, dec_hidden, W_proj, b_proj, p_rep);

    // 3) build x_cat: char half + zero padded half, then ragged scatter
    build_char_kernel<<<(B_ * L_ * 32) / 256, 256>>>(ids, char_emb);
    scatter_pad_kernel<<<(B_ * N_ * 32) / 256, 256>>>(lens);

    // 4) LSTM input pre-GEMM: xpre = x_cat @ W_ih^T + (b_ih+b_hh)
    sgemm_bias_kernel<<<dim3(G4H_ / BN, (B_ * L_) / BM), 256>>>(
        B_ * L_, G4H_, 2 * CE_, p_xcat, p_WihT, p_bias2, p_xpre);

    // 5) recurrence (one CTA per batch)
    cudaFuncSetAttribute(lstm_rec_kernel,
                         cudaFuncAttributeMaxDynamicSharedMemorySize, LSTM_SMEM);
    lstm_rec_kernel<<<B_, 512, LSTM_SMEM>>>(W_hh);

    // 6) prediction GEMM: out = hs @ W_pred + b_pred   [32768,128]@[128,1024]
    sgemm_bias_kernel<<<dim3(VOCAB_ / BN, (B_ * L_) / BM), 256>>>(
        B_ * L_, VOCAB_, H_, p_hs, W_pred, b_pred, out);
}

// round 8
// speedup vs baseline: 1.5792x; 1.1171x over previous
#include <cuda_runtime.h>
#include <cuda_bf16.h>

#define B_ 16
#define N_ 512
#define L_ 2048
#define DIM_ 768
#define M_ 8
#define CE_ 64
#define VOCAB_ 1024
#define H_ 128
#define G4H_ (4*H_)   // 512

// ---------------- scratch (device globals: no allocations allowed) ----------
__device__ float g_rep [B_*N_*M_*CE_];    // [B,N,512]  word char projections
__device__ float g_xcat[B_*L_*2*CE_];     // [B,L,128]  lstm input (char | padded)
__device__ float g_xpre[B_*L_*G4H_];      // [B,L,512]  x@W_ih^T + b_ih + b_hh
__device__ float g_hs  [B_*L_*H_];        // [B,L,128]  lstm hidden states
__device__ float g_WihT[2*CE_*G4H_];      // [128,512]  W_ih transposed
__device__ float g_bias2[G4H_];           // b_ih + b_hh
__device__ int   g_woff[B_*N_];           // exclusive prefix sum of word lens

// ---------------- f32x2 helpers ---------------------------------------------
static __device__ __forceinline__ unsigned long long pack2(float lo, float hi) {
    unsigned long long r;
    asm("mov.b64 %0, {%1, %2};" : "=l"(r) : "f"(lo), "f"(hi));
    return r;
}
static __device__ __forceinline__ unsigned long long pack2dup(float a) {
    unsigned long long r;
    asm("mov.b64 %0, {%1, %1};" : "=l"(r) : "f"(a));
    return r;
}
static __device__ __forceinline__ float2 unpack2(unsigned long long v) {
    float2 r;
    asm("mov.b64 {%0, %1}, %2;" : "=f"(r.x), "=f"(r.y) : "l"(v));
    return r;
}
static __device__ __forceinline__ unsigned long long ffma2(
    unsigned long long a, unsigned long long b, unsigned long long c) {
    unsigned long long d;
    asm("fma.rn.f32x2 %0, %1, %2, %3;" : "=l"(d) : "l"(a), "l"(b), "l"(c));
    return d;
}
static __device__ __forceinline__ float fast_tanh(float x) {
    float r;
    asm("tanh.approx.f32 %0, %1;" : "=f"(r) : "f"(x));
    return r;
}
static __device__ __forceinline__ float fast_sigmoid(float x) {
    // sigmoid(x) = 0.5 * tanh(x/2) + 0.5
    float r;
    asm("tanh.approx.f32 %0, %1;" : "=f"(r) : "f"(0.5f * x));
    return fmaf(0.5f, r, 0.5f);
}

// ---------------- prep: transpose W_ih, combine biases -----------------------
__global__ void prep_kernel(const float* __restrict__ W_ih,
                            const float* __restrict__ b_ih,
                            const float* __restrict__ b_hh) {
    int i = blockIdx.x * blockDim.x + threadIdx.x;
    if (i < G4H_ * 2 * CE_) {
        int g = i / (2 * CE_), k = i % (2 * CE_);
        g_WihT[k * G4H_ + g] = W_ih[g * (2 * CE_) + k];
    }
    if (i < G4H_) g_bias2[i] = b_ih[i] + b_hh[i];
}

// ---------------- per-batch exclusive prefix sum of word lens ---------------
__global__ void scan_lens_kernel(const int* __restrict__ lens) {
    __shared__ int s[N_];
    int b = blockIdx.x, tid = threadIdx.x;
    int v0 = lens[b * N_ + tid];
    s[tid] = v0;
    __syncthreads();
    #pragma unroll
    for (int off = 1; off < N_; off <<= 1) {
        int v = (tid >= off) ? s[tid - off] : 0;
        __syncthreads();
        s[tid] += v;
        __syncthreads();
    }
    g_woff[b * N_ + tid] = s[tid] - v0;   // exclusive
}

// ---------------- build x_cat: char embedding + zero padded half ------------
__global__ void build_char_kernel(const int* __restrict__ ids,
                                  const float* __restrict__ emb) {
    long i = (long)blockIdx.x * blockDim.x + threadIdx.x;   // one float4 each
    if (i >= (long)B_ * L_ * 32) return;
    int q = (int)(i & 31);
    long bt = i >> 5;
    float4* dst = (float4*)(g_xcat + bt * 128);
    if (q < 16) {
        int id = ids[bt];
        dst[q] = ((const float4*)(emb + (long)id * CE_))[q];
    } else {
        dst[q] = make_float4(0.f, 0.f, 0.f, 0.f);
    }
}

// ---------------- ragged scatter of word char projections -------------------
__global__ void scatter_pad_kernel(const int* __restrict__ lens) {
    int w = (blockIdx.x * blockDim.x + threadIdx.x) >> 5;   // one warp per word
    int lane = threadIdx.x & 31;
    if (w >= B_ * N_) return;
    int b = w / N_;
    int len = lens[w];
    int off = g_woff[w];
    for (int m = 0; m < len; m++) {
        int pos = off + m;
        if (pos >= L_) break;
        const float2* src = (const float2*)(g_rep + ((long)w * M_ + m) * CE_);
        float2* dst = (float2*)(g_xcat + ((long)b * L_ + pos) * 128 + CE_);
        dst[lane] = src[lane];
    }
}

// ---------------- fp32 GEMM (f32x2 FFMA), C = A@B + bias --------------------
// A [M,K] row-major, B [K,N] row-major, all tile dims divide exactly.
#define BM 128
#define BN 128
#define BK 16

__global__ __launch_bounds__(256, 2)
void sgemm_bias_kernel(int M, int N, int K,
                       const float* __restrict__ A,
                       const float* __restrict__ B,
                       const float* __restrict__ bias,
                       float* __restrict__ C) {
    __shared__ float As[BK][BM];
    __shared__ float Bs[BK][BN];
    int tid = threadIdx.x;
    int bx = blockIdx.x, by = blockIdx.y;
    int tx = tid & 15, ty = tid >> 4;

    const float* Ablk = A + (long)by * BM * K;
    const float* Bblk = B + bx * BN;

    unsigned long long acc[8][4];
    #pragma unroll
    for (int i = 0; i < 8; i++)
        #pragma unroll
        for (int j = 0; j < 4; j++) acc[i][j] = 0ull;   // two packed +0.0f

    int arow = tid >> 2;          // 0..63 (and +64)
    int acol4 = tid & 3;          // 0..3
    int brow = tid >> 5;          // 0..7 (and +8)
    int bcol4 = tid & 31;         // 0..31

    for (int k0 = 0; k0 < K; k0 += BK) {
        float4 a0 = *(const float4*)(Ablk + (long)arow * K + k0 + 4 * acol4);
        float4 a1 = *(const float4*)(Ablk + (long)(arow + 64) * K + k0 + 4 * acol4);
        float4 b0 = *(const float4*)(Bblk + (long)(k0 + brow) * N + 4 * bcol4);
        float4 b1 = *(const float4*)(Bblk + (long)(k0 + brow + 8) * N + 4 * bcol4);
        __syncthreads();
        As[4 * acol4 + 0][arow] = a0.x;
        As[4 * acol4 + 1][arow] = a0.y;
        As[4 * acol4 + 2][arow] = a0.z;
        As[4 * acol4 + 3][arow] = a0.w;
        As[4 * acol4 + 0][arow + 64] = a1.x;
        As[4 * acol4 + 1][arow + 64] = a1.y;
        As[4 * acol4 + 2][arow + 64] = a1.z;
        As[4 * acol4 + 3][arow + 64] = a1.w;
        *(float4*)&Bs[brow][4 * bcol4] = b0;
        *(float4*)&Bs[brow + 8][4 * bcol4] = b1;
        __syncthreads();
        #pragma unroll
        for (int k = 0; k < BK; k++) {
            float4 af0 = *(const float4*)&As[k][4 * ty];
            float4 af1 = *(const float4*)&As[k][64 + 4 * ty];
            ulonglong2 bf0 = *(const ulonglong2*)&Bs[k][4 * tx];
            ulonglong2 bf1 = *(const ulonglong2*)&Bs[k][64 + 4 * tx];
            float ar[8] = {af0.x, af0.y, af0.z, af0.w, af1.x, af1.y, af1.z, af1.w};
            unsigned long long b2[4] = {bf0.x, bf0.y, bf1.x, bf1.y};
            #pragma unroll
            for (int i = 0; i < 8; i++) {
                unsigned long long ad = pack2dup(ar[i]);
                #pragma unroll
                for (int j = 0; j < 4; j++)
                    acc[i][j] = ffma2(ad, b2[j], acc[i][j]);
            }
        }
    }

    #pragma unroll
    for (int i = 0; i < 8; i++) {
        int r = by * BM + (i < 4 ? 4 * ty + i : 64 + 4 * ty + (i - 4));
        #pragma unroll
        for (int j2 = 0; j2 < 4; j2++) {
            int cb = bx * BN + (j2 < 2 ? 4 * tx + 2 * j2 : 64 + 4 * tx + 2 * (j2 - 2));
            float2 v = unpack2(acc[i][j2]);
            float2 o;
            o.x = v.x + bias[cb];
            o.y = v.y + bias[cb + 1];
            *(float2*)&C[(long)r * N + cb] = o;
        }
    }
}

// ---------------- LSTM recurrence: one CTA per batch, 2-way K-split ---------
// 512 threads. Thread (q = tid>>8, i2 = tid&255) computes gate rows r0=2*i2,
// r1=2*i2+1 over k in [64q, 64q+64). q is warp-uniform -> h reads stay
// broadcast but HALVE (16 LDS.128/thread). Weights: r0 full (32 ull) + r1
// first 32 (16 ull) in registers; r1 last 32 floats in smem, k-major float2
// (lane-contiguous LDS.64, conflict-free). Two psum halves combined in the
// h-update phase (no extra barrier).
#define WSM2_FLOAT2 (2 * 16 * 256)                       // [q][kp][i2]
#define PSUM_OFF    (WSM2_FLOAT2 * 8)                    // bytes
#define HSM_OFF     (PSUM_OFF + 2 * G4H_ * 4)
#define LSTM_SMEM   (HSM_OFF + H_ * 4 + 128)

__global__ __launch_bounds__(512, 1)
void lstm_rec_kernel(const float* __restrict__ Whh) {
    extern __shared__ char smem_raw[];
    float2* wsm2 = (float2*)smem_raw;                    // [2*16*256]
    float*  psum = (float*)(smem_raw + PSUM_OFF);        // [2*512]
    float*  h_sm = (float*)(smem_raw + HSM_OFF);         // [128]

    int b = blockIdx.x, tid = threadIdx.x;
    int q  = tid >> 8;         // k-half
    int i2 = tid & 255;        // row-pair index
    int r0 = 2 * i2, r1 = r0 + 1;
    int kb = 64 * q;

    // --- preload weights ---
    const float* w0base = Whh + (long)r0 * H_ + kb;
    const float* w1base = Whh + (long)r1 * H_ + kb;
    unsigned long long w0[32], w1[16];
    #pragma unroll
    for (int k2 = 0; k2 < 32; k2++) w0[k2] = ((const unsigned long long*)w0base)[k2];
    #pragma unroll
    for (int k2 = 0; k2 < 16; k2++) w1[k2] = ((const unsigned long long*)w1base)[k2];
    // r1 k rel [32,64) -> smem, k-major: wsm2[(q*16+kp)*256 + i2] = W[r1][kb+32+2kp..+1]
    #pragma unroll
    for (int kp = 0; kp < 16; kp++)
        wsm2[(q * 16 + kp) * 256 + i2] = ((const float2*)(w1base + 32))[kp];

    float c = 0.f;
    if (tid < H_) h_sm[tid] = 0.f;
    __syncthreads();

    const float* xp = g_xpre + (long)b * L_ * G4H_ + r0;   // q==0 threads only
    float2 xr = make_float2(0.f, 0.f);
    if (q == 0) xr = *(const float2*)xp;

    for (int t = 0; t < L_; t++) {
        int tn = (t + 1 < L_) ? t + 1 : t;
        float2 xnext = make_float2(0.f, 0.f);
        if (q == 0) xnext = *(const float2*)(xp + (long)tn * G4H_);

        unsigned long long acc0 = pack2(xr.x, 0.f);
        unsigned long long acc1 = pack2(xr.y, 0.f);
        const ulonglong2* h2 = (const ulonglong2*)(h_sm + kb);   // 16 x 16B broadcast

        #pragma unroll
        for (int k4 = 0; k4 < 8; k4++) {              // k rel [0,32): both rows from regs
            ulonglong2 hv = h2[k4];
            acc0 = ffma2(hv.x, w0[2 * k4], acc0);
            acc0 = ffma2(hv.y, w0[2 * k4 + 1], acc0);
            acc1 = ffma2(hv.x, w1[2 * k4], acc1);
            acc1 = ffma2(hv.y, w1[2 * k4 + 1], acc1);
        }
        #pragma unroll
        for (int k4 = 8; k4 < 16; k4++) {             // k rel [32,64): r1 from smem
            ulonglong2 hv = h2[k4];
            int kp = 2 * (k4 - 8);
            float2 wa = wsm2[(q * 16 + kp) * 256 + i2];
            float2 wb = wsm2[(q * 16 + kp + 1) * 256 + i2];
            acc0 = ffma2(hv.x, w0[2 * k4], acc0);
            acc0 = ffma2(hv.y, w0[2 * k4 + 1], acc0);
            acc1 = ffma2(hv.x, pack2(wa.x, wa.y), acc1);
            acc1 = ffma2(hv.y, pack2(wb.x, wb.y), acc1);
        }
        float2 a0 = unpack2(acc0), a1 = unpack2(acc1);
        *(float2*)&psum[q * G4H_ + r0] = make_float2(a0.x + a0.y, a1.x + a1.y);
        __syncthreads();

        if (tid < H_) {
            float gi = psum[tid]            + psum[G4H_ + tid];
            float gf = psum[H_ + tid]       + psum[G4H_ + H_ + tid];
            float gg = psum[2 * H_ + tid]   + psum[G4H_ + 2 * H_ + tid];
            float go = psum[3 * H_ + tid]   + psum[G4H_ + 3 * H_ + tid];
            float si = fast_sigmoid(gi);
            float sf = fast_sigmoid(gf);
            float tg = fast_tanh(gg);
            float so = fast_sigmoid(go);
            c = sf * c + si * tg;
            float h = so * fast_tanh(c);
            h_sm[tid] = h;
            g_hs[((long)b * L_ + t) * H_ + tid] = h;
        }
        __syncthreads();
        xr = xnext;
    }
}

// ---------------- launch ----------------------------------------------------
extern "C" void kernel_launch(void* const* d_in, const int* in_sizes, int n_in,
                              void* d_out, int out_size) {
    const float* dec_hidden = (const float*)d_in[0];
    const int*   ids        = (const int*)d_in[1];
    const int*   lens       = (const int*)d_in[2];
    const float* char_emb   = (const float*)d_in[3];
    const float* W_proj     = (const float*)d_in[4];
    const float* b_proj     = (const float*)d_in[5];
    const float* W_ih       = (const float*)d_in[6];
    const float* W_hh       = (const float*)d_in[7];
    const float* b_ih       = (const float*)d_in[8];
    const float* b_hh       = (const float*)d_in[9];
    const float* W_pred     = (const float*)d_in[10];
    const float* b_pred     = (const float*)d_in[11];
    float* out = (float*)d_out;

    // device-global scratch addresses (host side)
    float *p_rep, *p_xcat, *p_xpre, *p_hs, *p_WihT, *p_bias2;
    cudaGetSymbolAddress((void**)&p_rep,   g_rep);
    cudaGetSymbolAddress((void**)&p_xcat,  g_xcat);
    cudaGetSymbolAddress((void**)&p_xpre,  g_xpre);
    cudaGetSymbolAddress((void**)&p_hs,    g_hs);
    cudaGetSymbolAddress((void**)&p_WihT,  g_WihT);
    cudaGetSymbolAddress((void**)&p_bias2, g_bias2);

    // 0) prep: transpose W_ih, combine biases
    prep_kernel<<<(G4H_ * 2 * CE_ + 255) / 256, 256>>>(W_ih, b_ih, b_hh);

    // 1) word-length prefix sums
    scan_lens_kernel<<<B_, N_>>>(lens);

    // 2) proj GEMM: rep = dec_hidden @ W_proj + b_proj   [8192,768]@[768,512]
    sgemm_bias_kernel<<<dim3(G4H_ / BN, (B_ * N_) / BM), 256>>>(
        B_ * N_, M_ * CE_, DIM_, dec_hidden, W_proj, b_proj, p_rep);

    // 3) build x_cat: char half + zero padded half, then ragged scatter
    build_char_kernel<<<(B_ * L_ * 32) / 256, 256>>>(ids, char_emb);
    scatter_pad_kernel<<<(B_ * N_ * 32) / 256, 256>>>(lens);

    // 4) LSTM input pre-GEMM: xpre = x_cat @ W_ih^T + (b_ih+b_hh)
    sgemm_bias_kernel<<<dim3(G4H_ / BN, (B_ * L_) / BM), 256>>>(
        B_ * L_, G4H_, 2 * CE_, p_xcat, p_WihT, p_bias2, p_xpre);

    // 5) recurrence (one CTA per batch)
    cudaFuncSetAttribute(lstm_rec_kernel,
                         cudaFuncAttributeMaxDynamicSharedMemorySize, LSTM_SMEM);
    lstm_rec_kernel<<<B_, 512, LSTM_SMEM>>>(W_hh);

    // 6) prediction GEMM: out = hs @ W_pred + b_pred   [32768,128]@[128,1024]
    sgemm_bias_kernel<<<dim3(VOCAB_ / BN, (B_ * L_) / BM), 256>>>(
        B_ * L_, VOCAB_, H_, p_hs, W_pred, b_pred, out);
}

// round 10
// speedup vs baseline: 1.8149x; 1.1493x over previous
#include <cuda_runtime.h>
#include <cuda_bf16.h>

#define B_ 16
#define N_ 512
#define L_ 2048
#define DIM_ 768
#define M_ 8
#define CE_ 64
#define VOCAB_ 1024
#define H_ 128
#define G4H_ (4*H_)   // 512

// ---------------- scratch (device globals: no allocations allowed) ----------
__device__ float g_rep [B_*N_*M_*CE_];    // [B,N,512]  word char projections
__device__ float g_xcat[B_*L_*2*CE_];     // [B,L,128]  lstm input (char | padded)
__device__ float g_xpre[B_*L_*G4H_];      // [B,L,512]  x@W_ih^T + b_ih + b_hh
__device__ float g_hs  [B_*L_*H_];        // [B,L,128]  lstm hidden states
__device__ float g_WprojT[G4H_*DIM_];     // [512,768]  W_proj transposed (N,K)
__device__ float g_WpredT[VOCAB_*H_];     // [1024,128] W_pred transposed (N,K)
__device__ float g_bias2[G4H_];           // b_ih + b_hh
__device__ int   g_woff[B_*N_];           // exclusive prefix sum of word lens

// ---------------- f32x2 / misc helpers ---------------------------------------
static __device__ __forceinline__ unsigned long long pack2(float lo, float hi) {
    unsigned long long r;
    asm("mov.b64 %0, {%1, %2};" : "=l"(r) : "f"(lo), "f"(hi));
    return r;
}
static __device__ __forceinline__ float2 unpack2(unsigned long long v) {
    float2 r;
    asm("mov.b64 {%0, %1}, %2;" : "=f"(r.x), "=f"(r.y) : "l"(v));
    return r;
}
static __device__ __forceinline__ unsigned long long ffma2(
    unsigned long long a, unsigned long long b, unsigned long long c) {
    unsigned long long d;
    asm("fma.rn.f32x2 %0, %1, %2, %3;" : "=l"(d) : "l"(a), "l"(b), "l"(c));
    return d;
}
static __device__ __forceinline__ float fast_tanh(float x) {
    float r;
    asm("tanh.approx.f32 %0, %1;" : "=f"(r) : "f"(x));
    return r;
}
static __device__ __forceinline__ float fast_sigmoid(float x) {
    float r;
    asm("tanh.approx.f32 %0, %1;" : "=f"(r) : "f"(0.5f * x));
    return fmaf(0.5f, r, 0.5f);
}
static __device__ __forceinline__ unsigned tf32_of(float f) {
    unsigned u;
    asm("cvt.rna.tf32.f32 %0, %1;" : "=r"(u) : "f"(f));
    return u;
}
static __device__ __forceinline__ unsigned smem_u32(const void* p) {
    return (unsigned)__cvta_generic_to_shared(p);
}

// ---------------- prep: combine biases ---------------------------------------
__global__ void prep_bias_kernel(const float* __restrict__ b_ih,
                                 const float* __restrict__ b_hh) {
    int i = blockIdx.x * blockDim.x + threadIdx.x;
    if (i < G4H_) g_bias2[i] = b_ih[i] + b_hh[i];
}

// ---------------- tiled transpose: dst[C][R] = src[R][C] ---------------------
__global__ void transpose_kernel(const float* __restrict__ src,
                                 float* __restrict__ dst, int R, int C) {
    __shared__ float t[32][33];
    int bx = blockIdx.x * 32, by = blockIdx.y * 32;
    int x = bx + threadIdx.x;
    #pragma unroll
    for (int dy = 0; dy < 32; dy += 8)
        t[threadIdx.y + dy][threadIdx.x] = src[(long)(by + threadIdx.y + dy) * C + x];
    __syncthreads();
    int x2 = by + threadIdx.x;
    #pragma unroll
    for (int dy = 0; dy < 32; dy += 8)
        dst[(long)(bx + threadIdx.y + dy) * R + x2] = t[threadIdx.x][threadIdx.y + dy];
}

// ---------------- per-batch exclusive prefix sum of word lens ---------------
__global__ void scan_lens_kernel(const int* __restrict__ lens) {
    __shared__ int s[N_];
    int b = blockIdx.x, tid = threadIdx.x;
    int v0 = lens[b * N_ + tid];
    s[tid] = v0;
    __syncthreads();
    #pragma unroll
    for (int off = 1; off < N_; off <<= 1) {
        int v = (tid >= off) ? s[tid - off] : 0;
        __syncthreads();
        s[tid] += v;
        __syncthreads();
    }
    g_woff[b * N_ + tid] = s[tid] - v0;   // exclusive
}

// ---------------- build x_cat: char embedding + zero padded half ------------
__global__ void build_char_kernel(const int* __restrict__ ids,
                                  const float* __restrict__ emb) {
    long i = (long)blockIdx.x * blockDim.x + threadIdx.x;   // one float4 each
    if (i >= (long)B_ * L_ * 32) return;
    int q = (int)(i & 31);
    long bt = i >> 5;
    float4* dst = (float4*)(g_xcat + bt * 128);
    if (q < 16) {
        int id = ids[bt];
        dst[q] = ((const float4*)(emb + (long)id * CE_))[q];
    } else {
        dst[q] = make_float4(0.f, 0.f, 0.f, 0.f);
    }
}

// ---------------- ragged scatter of word char projections -------------------
__global__ void scatter_pad_kernel(const int* __restrict__ lens) {
    int w = (blockIdx.x * blockDim.x + threadIdx.x) >> 5;   // one warp per word
    int lane = threadIdx.x & 31;
    if (w >= B_ * N_) return;
    int b = w / N_;
    int len = lens[w];
    int off = g_woff[w];
    for (int m = 0; m < len; m++) {
        int pos = off + m;
        if (pos >= L_) break;
        const float2* src = (const float2*)(g_rep + ((long)w * M_ + m) * CE_);
        float2* dst = (float2*)(g_xcat + ((long)b * L_ + pos) * 128 + CE_);
        dst[lane] = src[lane];
    }
}

// ---------------- tf32 tensor-core GEMM: C = A @ Bt^T + bias -----------------
// A [M,K] row-major, Bt [N,K] row-major (i.e. B pre-transposed), via
// mma.sync.aligned.m16n8k8.row.col.f32.tf32.tf32.f32.
// CTA tile 128x128, BK=16, 8 warps in 4(m) x 2(n) -> warp tile 32x64.
#define GSTR 20   // padded smem row stride in floats (8 rows * 20 -> distinct banks)

static __device__ __forceinline__ void ldsm_x4(unsigned& r0, unsigned& r1,
                                               unsigned& r2, unsigned& r3, unsigned addr) {
    asm volatile("ldmatrix.sync.aligned.m8n8.x4.shared.b16 {%0,%1,%2,%3}, [%4];"
                 : "=r"(r0), "=r"(r1), "=r"(r2), "=r"(r3) : "r"(addr));
}
static __device__ __forceinline__ void ldsm_x2(unsigned& r0, unsigned& r1, unsigned addr) {
    asm volatile("ldmatrix.sync.aligned.m8n8.x2.shared.b16 {%0,%1}, [%2];"
                 : "=r"(r0), "=r"(r1) : "r"(addr));
}
static __device__ __forceinline__ void mma_tf32(float* c, const unsigned* a, const unsigned* b) {
    asm volatile("mma.sync.aligned.m16n8k8.row.col.f32.tf32.tf32.f32 "
                 "{%0,%1,%2,%3}, {%4,%5,%6,%7}, {%8,%9}, {%0,%1,%2,%3};"
                 : "+f"(c[0]), "+f"(c[1]), "+f"(c[2]), "+f"(c[3])
                 : "r"(a[0]), "r"(a[1]), "r"(a[2]), "r"(a[3]), "r"(b[0]), "r"(b[1]));
}

__global__ __launch_bounds__(256)
void tf32_gemm_kernel(int M, int N, int K,
                      const float* __restrict__ A,
                      const float* __restrict__ Bt,
                      const float* __restrict__ bias,
                      float* __restrict__ C) {
    __shared__ unsigned As[128 * GSTR];
    __shared__ unsigned Bs[128 * GSTR];
    int tid = threadIdx.x, lane = tid & 31, wid = tid >> 5;
    int bm = blockIdx.y, bn = blockIdx.x;
    int wm = (wid >> 1) * 32;      // warp m offset within tile
    int wn = (wid & 1) * 64;       // warp n offset within tile

    // global loaders: each thread 2 rows of A and 2 rows of Bt (float4 each)
    int lr = tid >> 2, lk = (tid & 3) * 4;
    const float* Ag0 = A  + (long)(bm * 128 + lr) * K + lk;
    const float* Ag1 = Ag0 + (long)64 * K;
    const float* Bg0 = Bt + (long)(bn * 128 + lr) * K + lk;
    const float* Bg1 = Bg0 + (long)64 * K;

    // ldmatrix lane addresses
    int mat = lane >> 3;                            // 0..3 (A), &1 for B
    unsigned a_off = (unsigned)(((wm + (mat & 1) * 8 + (lane & 7)) * GSTR
                                + (mat >> 1) * 4) * 4);
    unsigned b_off = (unsigned)(((wn + (lane & 7)) * GSTR + (mat & 1) * 4) * 4);
    unsigned as_base = smem_u32(As);
    unsigned bs_base = smem_u32(Bs);

    float acc[2][8][4];
    #pragma unroll
    for (int i = 0; i < 2; i++)
        #pragma unroll
        for (int j = 0; j < 8; j++)
            #pragma unroll
            for (int v = 0; v < 4; v++) acc[i][j][v] = 0.f;

    float4 ra0 = *(const float4*)Ag0;
    float4 ra1 = *(const float4*)Ag1;
    float4 rb0 = *(const float4*)Bg0;
    float4 rb1 = *(const float4*)Bg1;

    unsigned* AsW0 = As + lr * GSTR + lk;
    unsigned* AsW1 = As + (lr + 64) * GSTR + lk;
    unsigned* BsW0 = Bs + lr * GSTR + lk;
    unsigned* BsW1 = Bs + (lr + 64) * GSTR + lk;

    for (int k0 = 0; k0 < K; k0 += 16) {
        __syncthreads();
        *(uint4*)AsW0 = make_uint4(tf32_of(ra0.x), tf32_of(ra0.y), tf32_of(ra0.z), tf32_of(ra0.w));
        *(uint4*)AsW1 = make_uint4(tf32_of(ra1.x), tf32_of(ra1.y), tf32_of(ra1.z), tf32_of(ra1.w));
        *(uint4*)BsW0 = make_uint4(tf32_of(rb0.x), tf32_of(rb0.y), tf32_of(rb0.z), tf32_of(rb0.w));
        *(uint4*)BsW1 = make_uint4(tf32_of(rb1.x), tf32_of(rb1.y), tf32_of(rb1.z), tf32_of(rb1.w));
        __syncthreads();

        if (k0 + 16 < K) {   // prefetch next tile (overlaps with mma below)
            Ag0 += 16; Ag1 += 16; Bg0 += 16; Bg1 += 16;
            ra0 = *(const float4*)Ag0;
            ra1 = *(const float4*)Ag1;
            rb0 = *(const float4*)Bg0;
            rb1 = *(const float4*)Bg1;
        }

        #pragma unroll
        for (int kk = 0; kk < 2; kk++) {
            unsigned koff = kk * 32;   // 8 floats = 32 bytes
            unsigned a[2][4];
            #pragma unroll
            for (int i = 0; i < 2; i++)
                ldsm_x4(a[i][0], a[i][1], a[i][2], a[i][3],
                        as_base + a_off + i * (16 * GSTR * 4) + koff);
            unsigned b[8][2];
            #pragma unroll
            for (int j = 0; j < 8; j++)
                ldsm_x2(b[j][0], b[j][1],
                        bs_base + b_off + j * (8 * GSTR * 4) + koff);
            #pragma unroll
            for (int i = 0; i < 2; i++)
                #pragma unroll
                for (int j = 0; j < 8; j++)
                    mma_tf32(acc[i][j], a[i], b[j]);
        }
    }

    // epilogue: c0,c1 -> row r0 cols (cb,cb+1); c2,c3 -> row r0+8
    #pragma unroll
    for (int i = 0; i < 2; i++) {
        int r0 = bm * 128 + wm + 16 * i + (lane >> 2);
        #pragma unroll
        for (int j = 0; j < 8; j++) {
            int cb = bn * 128 + wn + 8 * j + 2 * (lane & 3);
            float2 bv = *(const float2*)(bias + cb);
            float2 o0 = make_float2(acc[i][j][0] + bv.x, acc[i][j][1] + bv.y);
            float2 o1 = make_float2(acc[i][j][2] + bv.x, acc[i][j][3] + bv.y);
            *(float2*)&C[(long)r0 * N + cb] = o0;
            *(float2*)&C[(long)(r0 + 8) * N + cb] = o1;
        }
    }
}

// ---------------- LSTM recurrence: one CTA per batch, 2-way K-split ---------
// (unchanged from R8 — isolates the GEMM change)
#define WSM2_FLOAT2 (2 * 16 * 256)                       // [q][kp][i2]
#define PSUM_OFF    (WSM2_FLOAT2 * 8)                    // bytes
#define HSM_OFF     (PSUM_OFF + 2 * G4H_ * 4)
#define LSTM_SMEM   (HSM_OFF + H_ * 4 + 128)

__global__ __launch_bounds__(512, 1)
void lstm_rec_kernel(const float* __restrict__ Whh) {
    extern __shared__ char smem_raw[];
    float2* wsm2 = (float2*)smem_raw;                    // [2*16*256]
    float*  psum = (float*)(smem_raw + PSUM_OFF);        // [2*512]
    float*  h_sm = (float*)(smem_raw + HSM_OFF);         // [128]

    int b = blockIdx.x, tid = threadIdx.x;
    int q  = tid >> 8;         // k-half
    int i2 = tid & 255;        // row-pair index
    int r0 = 2 * i2, r1 = r0 + 1;
    int kb = 64 * q;

    const float* w0base = Whh + (long)r0 * H_ + kb;
    const float* w1base = Whh + (long)r1 * H_ + kb;
    unsigned long long w0[32], w1[16];
    #pragma unroll
    for (int k2 = 0; k2 < 32; k2++) w0[k2] = ((const unsigned long long*)w0base)[k2];
    #pragma unroll
    for (int k2 = 0; k2 < 16; k2++) w1[k2] = ((const unsigned long long*)w1base)[k2];
    #pragma unroll
    for (int kp = 0; kp < 16; kp++)
        wsm2[(q * 16 + kp) * 256 + i2] = ((const float2*)(w1base + 32))[kp];

    float c = 0.f;
    if (tid < H_) h_sm[tid] = 0.f;
    __syncthreads();

    const float* xp = g_xpre + (long)b * L_ * G4H_ + r0;
    float2 xr = make_float2(0.f, 0.f);
    if (q == 0) xr = *(const float2*)xp;

    for (int t = 0; t < L_; t++) {
        int tn = (t + 1 < L_) ? t + 1 : t;
        float2 xnext = make_float2(0.f, 0.f);
        if (q == 0) xnext = *(const float2*)(xp + (long)tn * G4H_);

        unsigned long long acc0 = pack2(xr.x, 0.f);
        unsigned long long acc1 = pack2(xr.y, 0.f);
        const ulonglong2* h2 = (const ulonglong2*)(h_sm + kb);

        #pragma unroll
        for (int k4 = 0; k4 < 8; k4++) {
            ulonglong2 hv = h2[k4];
            acc0 = ffma2(hv.x, w0[2 * k4], acc0);
            acc0 = ffma2(hv.y, w0[2 * k4 + 1], acc0);
            acc1 = ffma2(hv.x, w1[2 * k4], acc1);
            acc1 = ffma2(hv.y, w1[2 * k4 + 1], acc1);
        }
        #pragma unroll
        for (int k4 = 8; k4 < 16; k4++) {
            ulonglong2 hv = h2[k4];
            int kp = 2 * (k4 - 8);
            float2 wa = wsm2[(q * 16 + kp) * 256 + i2];
            float2 wb = wsm2[(q * 16 + kp + 1) * 256 + i2];
            acc0 = ffma2(hv.x, w0[2 * k4], acc0);
            acc0 = ffma2(hv.y, w0[2 * k4 + 1], acc0);
            acc1 = ffma2(hv.x, pack2(wa.x, wa.y), acc1);
            acc1 = ffma2(hv.y, pack2(wb.x, wb.y), acc1);
        }
        float2 a0 = unpack2(acc0), a1 = unpack2(acc1);
        *(float2*)&psum[q * G4H_ + r0] = make_float2(a0.x + a0.y, a1.x + a1.y);
        __syncthreads();

        if (tid < H_) {
            float gi = psum[tid]            + psum[G4H_ + tid];
            float gf = psum[H_ + tid]       + psum[G4H_ + H_ + tid];
            float gg = psum[2 * H_ + tid]   + psum[G4H_ + 2 * H_ + tid];
            float go = psum[3 * H_ + tid]   + psum[G4H_ + 3 * H_ + tid];
            float si = fast_sigmoid(gi);
            float sf = fast_sigmoid(gf);
            float tg = fast_tanh(gg);
            float so = fast_sigmoid(go);
            c = sf * c + si * tg;
            float h = so * fast_tanh(c);
            h_sm[tid] = h;
            g_hs[((long)b * L_ + t) * H_ + tid] = h;
        }
        __syncthreads();
        xr = xnext;
    }
}

// ---------------- launch ----------------------------------------------------
extern "C" void kernel_launch(void* const* d_in, const int* in_sizes, int n_in,
                              void* d_out, int out_size) {
    const float* dec_hidden = (const float*)d_in[0];
    const int*   ids        = (const int*)d_in[1];
    const int*   lens       = (const int*)d_in[2];
    const float* char_emb   = (const float*)d_in[3];
    const float* W_proj     = (const float*)d_in[4];
    const float* b_proj     = (const float*)d_in[5];
    const float* W_ih       = (const float*)d_in[6];
    const float* W_hh       = (const float*)d_in[7];
    const float* b_ih       = (const float*)d_in[8];
    const float* b_hh       = (const float*)d_in[9];
    const float* W_pred     = (const float*)d_in[10];
    const float* b_pred     = (const float*)d_in[11];
    float* out = (float*)d_out;

    float *p_rep, *p_xcat, *p_xpre, *p_hs, *p_WprojT, *p_WpredT, *p_bias2;
    cudaGetSymbolAddress((void**)&p_rep,    g_rep);
    cudaGetSymbolAddress((void**)&p_xcat,   g_xcat);
    cudaGetSymbolAddress((void**)&p_xpre,   g_xpre);
    cudaGetSymbolAddress((void**)&p_hs,     g_hs);
    cudaGetSymbolAddress((void**)&p_WprojT, g_WprojT);
    cudaGetSymbolAddress((void**)&p_WpredT, g_WpredT);
    cudaGetSymbolAddress((void**)&p_bias2,  g_bias2);

    // 0) prep: combine biases; transpose W_proj [768,512]->[512,768],
    //    W_pred [128,1024]->[1024,128]. (W_ih is already [N,K]=[512,128].)
    prep_bias_kernel<<<(G4H_ + 255) / 256, 256>>>(b_ih, b_hh);
    transpose_kernel<<<dim3(G4H_ / 32, DIM_ / 32), dim3(32, 8)>>>(W_proj, p_WprojT, DIM_, G4H_);
    transpose_kernel<<<dim3(VOCAB_ / 32, H_ / 32), dim3(32, 8)>>>(W_pred, p_WpredT, H_, VOCAB_);

    // 1) word-length prefix sums
    scan_lens_kernel<<<B_, N_>>>(lens);

    // 2) proj GEMM: rep = dec_hidden @ W_proj + b_proj   [8192,768]x[768,512]
    tf32_gemm_kernel<<<dim3(G4H_ / 128, (B_ * N_) / 128), 256>>>(
        B_ * N_, G4H_, DIM_, dec_hidden, p_WprojT, b_proj, p_rep);

    // 3) build x_cat: char half + zero padded half, then ragged scatter
    build_char_kernel<<<(B_ * L_ * 32) / 256, 256>>>(ids, char_emb);
    scatter_pad_kernel<<<(B_ * N_ * 32) / 256, 256>>>(lens);

    // 4) LSTM input pre-GEMM: xpre = x_cat @ W_ih^T + (b_ih+b_hh)
    //    Bt = W_ih itself: [512,128] row-major = [N,K]
    tf32_gemm_kernel<<<dim3(G4H_ / 128, (B_ * L_) / 128), 256>>>(
        B_ * L_, G4H_, 2 * CE_, p_xcat, W_ih, p_bias2, p_xpre);

    // 5) recurrence (one CTA per batch)
    cudaFuncSetAttribute(lstm_rec_kernel,
                         cudaFuncAttributeMaxDynamicSharedMemorySize, LSTM_SMEM);
    lstm_rec_kernel<<<B_, 512, LSTM_SMEM>>>(W_hh);

    // 6) prediction GEMM: out = hs @ W_pred + b_pred   [32768,128]x[128,1024]
    tf32_gemm_kernel<<<dim3(VOCAB_ / 128, (B_ * L_) / 128), 256>>>(
        B_ * L_, VOCAB_, H_, p_hs, p_WpredT, b_pred, out);
}